// round 16
// baseline (speedup 1.0000x reference)
#include <cuda_runtime.h>
#include <stdint.h>

// QLayerOriginal: rho <- U rho U^dagger over 16 blocks of 3 angles.
// Exact reduction: on the complex Bloch vector t (rho = t0 I + t.sigma),
// conjugation by U(p0,p1,p2)=D(p1/2)R(p0/2)D(p2/2) is the REAL SO(3) map
// Rz(-p1) Ry(p0) Rz(-p2) on Re(t), Im(t); t0 invariant. Adjacent Rz fuse
// (zacc carries previous p1):
//   zacc=0; for k: Rz(-(zacc+phi[3k+2])); Ry(phi[3k]); zacc=phi[3k+1]; final Rz(-zacc).
//
// R16: PERSISTENT CTAs + cross-tile double-buffered cp.async pipeline.
// Two half-buffers (24 phi floats each, stride 28). Steady state per tile t:
//   wait(1) [A(t) ready, B(t) flying] -> compute blocks 0..7
//   restage A(t+G) into freed bufA    -> wait(1) [B(t) ready, A(t+G) flying]
//   compute blocks 8..15 + store      -> restage B(t+G)
// >=1 cp.async group always outstanding => DRAM never idles per-CTA.
// Same 96B chunk granularity as R14 (R15 showed finer slicing inflates L2).

#define NTHREADS 96
#define ROWS 96
#define HS 28                   // half-row stride in floats (16B-aligned, 4-way LDS ok)
#define MAXCTA 1480             // ~10 CTAs/SM * 148

__device__ __forceinline__ void cp_async16(uint32_t dst, const void* src) {
    asm volatile("cp.async.cg.shared.global [%0], [%1], 16;" :: "r"(dst), "l"(src));
}
#define CP_COMMIT()  asm volatile("cp.async.commit_group;" ::: "memory")
#define CP_WAIT(n)   asm volatile("cp.async.wait_group %0;" :: "n"(n) : "memory")

// stage one 24-float half (halfOff = 0 or 24) of tile rows into smem buffer
__device__ __forceinline__ void stage_half(uint32_t sbase, const float* xb,
                                           int nLocal, int halfOff, int tid) {
    int j6 = tid % 6;            // float4 index within the half
    int sq = tid / 6;            // 0..15
#pragma unroll
    for (int k = 0; k < 6; ++k) {
        int s = sq + 16 * k;
        if (s < nLocal)
            cp_async16(sbase + (uint32_t)(s * HS + j6 * 4) * 4u,
                       xb + s * 48 + halfOff + j6 * 4);
    }
}

__global__ void __launch_bounds__(NTHREADS) qlayer_kernel_vec(
    const float* __restrict__ rho_real,
    const float* __restrict__ rho_imag,
    const float* __restrict__ x,
    const float* __restrict__ w,
    const float* __restrict__ theta,
    float* __restrict__ out,
    long long nbatch,
    long long T,                 // number of 96-sample tiles
    long long out_elems,
    int full_complex)
{
    __shared__ float bufA[ROWS * HS];    // 10752 B
    __shared__ float bufB[ROWS * HS];    // 10752 B
    __shared__ float s_w[48];
    __shared__ float s_t[48];

    int tid = threadIdx.x;
    if (tid < 12) {
        ((float4*)s_w)[tid] = __ldg((const float4*)w + tid);
        ((float4*)s_t)[tid] = __ldg((const float4*)theta + tid);
    }

    uint32_t baseA = (uint32_t)__cvta_generic_to_shared(bufA);
    uint32_t baseB = (uint32_t)__cvta_generic_to_shared(bufB);
    long long G = gridDim.x;

    long long t = blockIdx.x;
    if (t >= T) return;

    // ---- prologue: stage both halves of first tile ----
    {
        const float* xb = x + t * (96LL * 48);
        int nL = (int)((nbatch - t * 96 < 96) ? (nbatch - t * 96) : 96);
        stage_half(baseA, xb, nL, 0, tid);  CP_COMMIT();
        stage_half(baseB, xb, nL, 24, tid); CP_COMMIT();
    }

    while (true) {
        long long base = t * 96;
        long long i = base + tid;
        bool active = (i < nbatch);
        long long ic = active ? i : 0;
        // rho loads issue before the wait -> overlap cp.async stall
        float4 rr = __ldcs((const float4*)rho_real + ic);
        float4 ri = __ldcs((const float4*)rho_imag + ic);

        long long tn = t + G;
        bool hasNext = (tn < T);

        CP_WAIT(1);              // A(t) complete; B(t) may still fly
        __syncthreads();

        // ---- phi-pass A (own row, float4, conflict-free per phase) ----
        float* rowA = &bufA[tid * HS];
        {
            float4* rv = (float4*)rowA;
#pragma unroll
            for (int j4 = 0; j4 < 6; ++j4) {
                float4 xv = rv[j4];
                float4 wv = ((const float4*)s_w)[j4];
                float4 tv = ((const float4*)s_t)[j4];
                rv[j4] = make_float4(fmaf(xv.x, wv.x, tv.x), fmaf(xv.y, wv.y, tv.y),
                                     fmaf(xv.z, wv.z, tv.z), fmaf(xv.w, wv.w, tv.w));
            }
        }

        // ---- Pauli decomposition ----
        float t0r = 0.5f * (rr.x + rr.w), t0i = 0.5f * (ri.x + ri.w);
        float vzr = 0.5f * (rr.x - rr.w), vzi = 0.5f * (ri.x - ri.w);
        float vxr = 0.5f * (rr.y + rr.z), vxi = 0.5f * (ri.y + ri.z);
        float vyr = 0.5f * (ri.z - ri.y), vyi = 0.5f * (rr.y - rr.z);

        float zacc = 0.0f;
        // ---- rotation blocks 0..7 ----
#pragma unroll
        for (int m = 0; m < 8; ++m) {
            float psi = zacc + rowA[3 * m + 2];
            float sz, cz;
            __sincosf(psi, &sz, &cz);
            {   // Rz(-psi): x' = c x + s y ; y' = c y - s x
                float nxr = cz * vxr + sz * vyr;
                float nyr = cz * vyr - sz * vxr;
                float nxi = cz * vxi + sz * vyi;
                float nyi = cz * vyi - sz * vxi;
                vxr = nxr; vyr = nyr; vxi = nxi; vyi = nyi;
            }
            float sy, cy;
            __sincosf(rowA[3 * m], &sy, &cy);
            {   // Ry(a): x' = c x + s z ; z' = c z - s x
                float nxr = cy * vxr + sy * vzr;
                float nzr = cy * vzr - sy * vxr;
                float nxi = cy * vxi + sy * vzi;
                float nzi = cy * vzi - sy * vxi;
                vxr = nxr; vzr = nzr; vxi = nxi; vzi = nzi;
            }
            zacc = rowA[3 * m + 1];
        }

        __syncthreads();         // everyone done reading bufA

        if (hasNext) {           // restage A(t+G) into freed bufA, then wait B(t)
            const float* xbn = x + tn * (96LL * 48);
            int nLn = (int)((nbatch - tn * 96 < 96) ? (nbatch - tn * 96) : 96);
            stage_half(baseA, xbn, nLn, 0, tid);
            CP_COMMIT();
            CP_WAIT(1);          // B(t) (older) complete; A(tn) may fly
        } else {
            CP_WAIT(0);
        }
        __syncthreads();

        // ---- phi-pass B ----
        float* rowB = &bufB[tid * HS];
        {
            float4* rv = (float4*)rowB;
#pragma unroll
            for (int j4 = 0; j4 < 6; ++j4) {
                float4 xv = rv[j4];
                float4 wv = ((const float4*)s_w)[6 + j4];
                float4 tv = ((const float4*)s_t)[6 + j4];
                rv[j4] = make_float4(fmaf(xv.x, wv.x, tv.x), fmaf(xv.y, wv.y, tv.y),
                                     fmaf(xv.z, wv.z, tv.z), fmaf(xv.w, wv.w, tv.w));
            }
        }

        // ---- rotation blocks 8..15 ----
#pragma unroll
        for (int m = 0; m < 8; ++m) {
            float psi = zacc + rowB[3 * m + 2];
            float sz, cz;
            __sincosf(psi, &sz, &cz);
            {
                float nxr = cz * vxr + sz * vyr;
                float nyr = cz * vyr - sz * vxr;
                float nxi = cz * vxi + sz * vyi;
                float nyi = cz * vyi - sz * vxi;
                vxr = nxr; vyr = nyr; vxi = nxi; vyi = nyi;
            }
            float sy, cy;
            __sincosf(rowB[3 * m], &sy, &cy);
            {
                float nxr = cy * vxr + sy * vzr;
                float nzr = cy * vzr - sy * vxr;
                float nxi = cy * vxi + sy * vzi;
                float nzi = cy * vzi - sy * vxi;
                vxr = nxr; vzr = nzr; vxi = nxi; vzi = nzi;
            }
            zacc = rowB[3 * m + 1];
        }
        {   // final Rz(-zacc)
            float sz, cz;
            __sincosf(zacc, &sz, &cz);
            float nxr = cz * vxr + sz * vyr;
            float nyr = cz * vyr - sz * vxr;
            float nxi = cz * vxi + sz * vyi;
            float nyi = cz * vyi - sz * vxi;
            vxr = nxr; vyr = nyr; vxi = nxi; vyi = nyi;
        }

        // ---- store: r00=t0+tz, r01=tx-i ty, r10=tx+i ty, r11=t0-tz ----
        if (active) {
            if (full_complex) {
                long long ob = i * 8;
                if (ob + 7 < out_elems) {
                    float4* op = (float4*)(out + ob);
                    __stcs(op + 0, make_float4(t0r + vzr, t0i + vzi, vxr + vyi, vxi - vyr));
                    __stcs(op + 1, make_float4(vxr - vyi, vxi + vyr, t0r - vzr, t0i - vzi));
                }
            } else {
                long long ob = i * 4;
                if (ob + 3 < out_elems) {
                    __stcs((float4*)(out + ob),
                           make_float4(t0r + vzr, vxr + vyi, vxr - vyi, t0r - vzr));
                }
            }
        }

        __syncthreads();         // everyone done reading bufB

        if (!hasNext) break;
        {   // restage B(t+G)
            const float* xbn = x + tn * (96LL * 48);
            int nLn = (int)((nbatch - tn * 96 < 96) ? (nbatch - tn * 96) : 96);
            stage_half(baseB, xbn, nLn, 24, tid);
            CP_COMMIT();
        }
        t = tn;
    }
}

// ---- scalar fallback (any alignment) ---------------------------------------
__global__ void __launch_bounds__(128) qlayer_kernel_scalar(
    const float* __restrict__ rho_real,
    const float* __restrict__ rho_imag,
    const float* __restrict__ x,
    const float* __restrict__ w,
    const float* __restrict__ theta,
    float* __restrict__ out,
    long long nbatch,
    long long out_elems,
    int full_complex)
{
    __shared__ float s_w[48];
    __shared__ float s_t[48];
    int tid = threadIdx.x;
    if (tid < 48) {
        s_w[tid] = w[tid];
        s_t[tid] = theta[tid];
    }
    __syncthreads();

    long long i = (long long)blockIdx.x * 128 + tid;
    if (i >= nbatch) return;

    const float* xr = x + i * 48;
#define PHI(j) fmaf(xr[(j)], s_w[(j)], s_t[(j)])

    const float* rrp = rho_real + i * 4;
    const float* rip = rho_imag + i * 4;
    float rr0 = rrp[0], rr1 = rrp[1], rr2 = rrp[2], rr3 = rrp[3];
    float ri0 = rip[0], ri1 = rip[1], ri2 = rip[2], ri3 = rip[3];

    float t0r = 0.5f * (rr0 + rr3), t0i = 0.5f * (ri0 + ri3);
    float vzr = 0.5f * (rr0 - rr3), vzi = 0.5f * (ri0 - ri3);
    float vxr = 0.5f * (rr1 + rr2), vxi = 0.5f * (ri1 + ri2);
    float vyr = 0.5f * (ri2 - ri1), vyi = 0.5f * (rr1 - rr2);

    float zacc = 0.0f;
#pragma unroll
    for (int k = 0; k < 16; ++k) {
        float psi = zacc + PHI(3 * k + 2);
        float sz, cz;
        __sincosf(psi, &sz, &cz);
        {
            float nxr = cz * vxr + sz * vyr;
            float nyr = cz * vyr - sz * vxr;
            float nxi = cz * vxi + sz * vyi;
            float nyi = cz * vyi - sz * vxi;
            vxr = nxr; vyr = nyr; vxi = nxi; vyi = nyi;
        }
        float sy, cy;
        __sincosf(PHI(3 * k), &sy, &cy);
        {
            float nxr = cy * vxr + sy * vzr;
            float nzr = cy * vzr - sy * vxr;
            float nxi = cy * vxi + sy * vzi;
            float nzi = cy * vzi - sy * vxi;
            vxr = nxr; vzr = nzr; vxi = nxi; vzi = nzi;
        }
        zacc = PHI(3 * k + 1);
    }
    {
        float sz, cz;
        __sincosf(zacc, &sz, &cz);
        float nxr = cz * vxr + sz * vyr;
        float nyr = cz * vyr - sz * vxr;
        float nxi = cz * vxi + sz * vyi;
        float nyi = cz * vyi - sz * vxi;
        vxr = nxr; vyr = nyr; vxi = nxi; vyi = nyi;
    }
#undef PHI

    if (full_complex) {
        long long base = i * 8;
        if (base + 7 < out_elems) {
            out[base + 0] = t0r + vzr; out[base + 1] = t0i + vzi;
            out[base + 2] = vxr + vyi; out[base + 3] = vxi - vyr;
            out[base + 4] = vxr - vyi; out[base + 5] = vxi + vyr;
            out[base + 6] = t0r - vzr; out[base + 7] = t0i - vzi;
        }
    } else {
        long long base = i * 4;
        if (base + 3 < out_elems) {
            out[base + 0] = t0r + vzr;
            out[base + 1] = vxr + vyi;
            out[base + 2] = vxr - vyi;
            out[base + 3] = t0r - vzr;
        }
    }
}

extern "C" void kernel_launch(void* const* d_in, const int* in_sizes, int n_in,
                              void* d_out, int out_size)
{
    const float* rho_real = nullptr;
    const float* rho_imag = nullptr;
    const float* x = nullptr;
    const float* w = nullptr;
    const float* theta = nullptr;
    long long B = 0;

    // 1) Strict metadata order (rho_real, rho_imag, x, w, theta).
    if (n_in >= 5) {
        long long s0 = in_sizes[0], s1 = in_sizes[1], s2 = in_sizes[2];
        long long s3 = in_sizes[3], s4 = in_sizes[4];
        if (s0 == s1 && s0 > 0 && (s0 % 4) == 0 &&
            s2 == 12 * s0 && s3 == 48 && s4 == 48) {
            rho_real = (const float*)d_in[0];
            rho_imag = (const float*)d_in[1];
            x        = (const float*)d_in[2];
            w        = (const float*)d_in[3];
            theta    = (const float*)d_in[4];
            B = s0 / 4;
        }
    }

    // 2) Fallback: consistency search over sizes.
    if (B == 0) {
        for (int a = 0; a < n_in && B == 0; ++a) {
            for (int b = a + 1; b < n_in && B == 0; ++b) {
                long long sa = in_sizes[a], sb = in_sizes[b];
                if (sa != sb || sa <= 0 || (sa % 4) != 0) continue;
                long long Bc = sa / 4;
                if (Bc < 2) continue;
                int xk = -1;
                for (int c = 0; c < n_in; ++c) {
                    if (c == a || c == b) continue;
                    if ((long long)in_sizes[c] == 48LL * Bc) { xk = c; break; }
                }
                if (xk < 0) continue;
                int s1i = -1, s2i = -1;
                for (int c = 0; c < n_in; ++c) {
                    if (c == a || c == b || c == xk) continue;
                    if (in_sizes[c] == 48) {
                        if (s1i < 0) s1i = c;
                        else if (s2i < 0) { s2i = c; break; }
                    }
                }
                if (s1i < 0 || s2i < 0) continue;
                rho_real = (const float*)d_in[a];
                rho_imag = (const float*)d_in[b];
                x        = (const float*)d_in[xk];
                w        = (const float*)d_in[s1i];
                theta    = (const float*)d_in[s2i];
                B = Bc;
            }
        }
    }

    float* out = (float*)d_out;
    long long out_elems = (long long)out_size;
    int full_complex = (B > 0 && out_elems >= 8 * B) ? 1 : 0;

    bool aligned =
        (((uintptr_t)x        & 15) == 0) &&
        (((uintptr_t)rho_real & 15) == 0) &&
        (((uintptr_t)rho_imag & 15) == 0) &&
        (((uintptr_t)w        & 15) == 0) &&
        (((uintptr_t)theta    & 15) == 0) &&
        (((uintptr_t)out      & 15) == 0);

    if (B > 0 && aligned) {
        long long T = (B + 95) / 96;
        unsigned nblk = (unsigned)((T < MAXCTA) ? T : MAXCTA);
        qlayer_kernel_vec<<<nblk, NTHREADS>>>(rho_real, rho_imag, x, w, theta, out,
                                              B, T, out_elems, full_complex);
    } else {
        unsigned nblk = (unsigned)(B > 0 ? (B + 127) / 128 : 1);
        qlayer_kernel_scalar<<<nblk, 128>>>(rho_real, rho_imag, x, w, theta, out,
                                            B, out_elems, full_complex);
    }
}

// round 17
// speedup vs baseline: 1.2221x; 1.2221x over previous
#include <cuda_runtime.h>
#include <stdint.h>

// QLayerOriginal: rho <- U rho U^dagger over 16 blocks of 3 angles.
// Exact reduction: on the complex Bloch vector t (rho = t0 I + t.sigma),
// conjugation by U(p0,p1,p2)=D(p1/2)R(p0/2)D(p2/2) is the REAL SO(3) map
// Rz(-p1) Ry(p0) Rz(-p2) on Re(t), Im(t); t0 invariant. Adjacent Rz fuse
// (zacc carries previous p1):
//   zacc=0; for k: Rz(-(zacc+phi[3k+2])); Ry(phi[3k]); zacc=phi[3k+1]; final Rz(-zacc).
//
// R17: R14's split-arrival pipeline extended to TWO tiles per CTA (4 rolling
// cp.async groups A0,B0,A1,B1 over the same two half-buffers). Memory stays in
// flight during 3 of 4 compute segments (R14: 1 of 2). Non-persistent, grid
// ~5462 -> many waves (R16's single-wave imbalance avoided). Same 96B chunk
// granularity, same 21.9KB smem.

#define NTHREADS 96
#define ROWS 96
#define HS 28                   // half-row stride in floats (16B-aligned cp.async dst)

__device__ __forceinline__ void cp_async16(uint32_t dst, const void* src) {
    asm volatile("cp.async.cg.shared.global [%0], [%1], 16;" :: "r"(dst), "l"(src));
}
#define CP_COMMIT()  asm volatile("cp.async.commit_group;" ::: "memory")
#define CP_WAIT(n)   asm volatile("cp.async.wait_group %0;" :: "n"(n) : "memory")

// stage one 24-float half (halfOff = 0 or 24) of a 96-sample tile
__device__ __forceinline__ void stage_half(uint32_t sbase, const float* xb,
                                           int nLocal, int halfOff, int tid) {
    int j6 = tid % 6;
    int sq = tid / 6;
#pragma unroll
    for (int k = 0; k < 6; ++k) {
        int s = sq + 16 * k;
        if (s < nLocal)
            cp_async16(sbase + (uint32_t)(s * HS + j6 * 4) * 4u,
                       xb + s * 48 + halfOff + j6 * 4);
    }
}

// in-place phi-pass on own row (float4, conflict-free per phase)
__device__ __forceinline__ void phi_pass(float* row, const float* s_w,
                                         const float* s_t, int halfIdx) {
    float4* rv = (float4*)row;
#pragma unroll
    for (int j4 = 0; j4 < 6; ++j4) {
        float4 xv = rv[j4];
        float4 wv = ((const float4*)s_w)[halfIdx * 6 + j4];
        float4 tv = ((const float4*)s_t)[halfIdx * 6 + j4];
        rv[j4] = make_float4(fmaf(xv.x, wv.x, tv.x), fmaf(xv.y, wv.y, tv.y),
                             fmaf(xv.z, wv.z, tv.z), fmaf(xv.w, wv.w, tv.w));
    }
}

// 8 rotation blocks from row (24 phi values)
__device__ __forceinline__ void rot8(const float* row, float& zacc,
                                     float& vxr, float& vyr, float& vzr,
                                     float& vxi, float& vyi, float& vzi) {
#pragma unroll
    for (int m = 0; m < 8; ++m) {
        float psi = zacc + row[3 * m + 2];
        float sz, cz;
        __sincosf(psi, &sz, &cz);
        {   // Rz(-psi): x' = c x + s y ; y' = c y - s x
            float nxr = cz * vxr + sz * vyr;
            float nyr = cz * vyr - sz * vxr;
            float nxi = cz * vxi + sz * vyi;
            float nyi = cz * vyi - sz * vxi;
            vxr = nxr; vyr = nyr; vxi = nxi; vyi = nyi;
        }
        float sy, cy;
        __sincosf(row[3 * m], &sy, &cy);
        {   // Ry(a): x' = c x + s z ; z' = c z - s x
            float nxr = cy * vxr + sy * vzr;
            float nzr = cy * vzr - sy * vxr;
            float nxi = cy * vxi + sy * vzi;
            float nzi = cy * vzi - sy * vxi;
            vxr = nxr; vzr = nzr; vxi = nxi; vzi = nzi;
        }
        zacc = row[3 * m + 1];
    }
}

__global__ void __launch_bounds__(NTHREADS) qlayer_kernel_vec(
    const float* __restrict__ rho_real,
    const float* __restrict__ rho_imag,
    const float* __restrict__ x,
    const float* __restrict__ w,
    const float* __restrict__ theta,
    float* __restrict__ out,
    long long nbatch,
    long long T,
    long long out_elems,
    int full_complex)
{
    __shared__ float bufA[ROWS * HS];
    __shared__ float bufB[ROWS * HS];
    __shared__ float s_w[48];
    __shared__ float s_t[48];

    int tid = threadIdx.x;
    if (tid < 12) {
        ((float4*)s_w)[tid] = __ldg((const float4*)w + tid);
        ((float4*)s_t)[tid] = __ldg((const float4*)theta + tid);
    }
    uint32_t baseA = (uint32_t)__cvta_generic_to_shared(bufA);
    uint32_t baseB = (uint32_t)__cvta_generic_to_shared(bufB);

    long long t0 = 2LL * blockIdx.x;
    long long t1 = t0 + 1;
    bool hasT1 = (t1 < T);

    const float* xb0 = x + t0 * (96LL * 48);
    int nL0 = (int)((nbatch - t0 * 96 < 96) ? (nbatch - t0 * 96) : 96);

    stage_half(baseA, xb0, nL0, 0, tid);  CP_COMMIT();   // G1 = A0
    stage_half(baseB, xb0, nL0, 24, tid); CP_COMMIT();   // G2 = B0

    long long i0 = t0 * 96 + tid;
    bool act0 = (i0 < nbatch);
    float4 rr = __ldcs((const float4*)rho_real + (act0 ? i0 : 0));
    float4 ri = __ldcs((const float4*)rho_imag + (act0 ? i0 : 0));

    CP_WAIT(1);                  // A0 done; B0 may fly
    __syncthreads();

    float* rowA = &bufA[tid * HS];
    float* rowB = &bufB[tid * HS];

    phi_pass(rowA, s_w, s_t, 0);

    float t0r = 0.5f * (rr.x + rr.w), t0i = 0.5f * (ri.x + ri.w);
    float vzr = 0.5f * (rr.x - rr.w), vzi = 0.5f * (ri.x - ri.w);
    float vxr = 0.5f * (rr.y + rr.z), vxi = 0.5f * (ri.y + ri.z);
    float vyr = 0.5f * (ri.z - ri.y), vyi = 0.5f * (rr.y - rr.z);
    float zacc = 0.0f;

    rot8(rowA, zacc, vxr, vyr, vzr, vxi, vyi, vzi);

    __syncthreads();             // done reading bufA

    const float* xb1 = x + t1 * (96LL * 48);
    int nL1 = 0;
    if (hasT1) {
        nL1 = (int)((nbatch - t1 * 96 < 96) ? (nbatch - t1 * 96) : 96);
        stage_half(baseA, xb1, nL1, 0, tid);  CP_COMMIT();  // G3 = A1
        CP_WAIT(1);              // B0 done; A1 may fly
    } else {
        CP_WAIT(0);
    }
    __syncthreads();

    phi_pass(rowB, s_w, s_t, 1);
    rot8(rowB, zacc, vxr, vyr, vzr, vxi, vyi, vzi);
    {   // final Rz(-zacc)
        float sz, cz;
        __sincosf(zacc, &sz, &cz);
        float nxr = cz * vxr + sz * vyr;
        float nyr = cz * vyr - sz * vxr;
        float nxi = cz * vxi + sz * vyi;
        float nyi = cz * vyi - sz * vxi;
        vxr = nxr; vyr = nyr; vxi = nxi; vyi = nyi;
    }

    // ---- store tile 0 ----
    if (act0) {
        if (full_complex) {
            long long ob = i0 * 8;
            if (ob + 7 < out_elems) {
                float4* op = (float4*)(out + ob);
                __stcs(op + 0, make_float4(t0r + vzr, t0i + vzi, vxr + vyi, vxi - vyr));
                __stcs(op + 1, make_float4(vxr - vyi, vxi + vyr, t0r - vzr, t0i - vzi));
            }
        } else {
            long long ob = i0 * 4;
            if (ob + 3 < out_elems) {
                __stcs((float4*)(out + ob),
                       make_float4(t0r + vzr, vxr + vyi, vxr - vyi, t0r - vzr));
            }
        }
    }

    if (!hasT1) return;

    __syncthreads();             // done reading bufB
    stage_half(baseB, xb1, nL1, 24, tid); CP_COMMIT();   // G4 = B1

    long long i1 = t1 * 96 + tid;
    bool act1 = (i1 < nbatch);
    rr = __ldcs((const float4*)rho_real + (act1 ? i1 : 0));
    ri = __ldcs((const float4*)rho_imag + (act1 ? i1 : 0));

    CP_WAIT(1);                  // A1 done; B1 may fly
    __syncthreads();

    phi_pass(rowA, s_w, s_t, 0);

    t0r = 0.5f * (rr.x + rr.w); t0i = 0.5f * (ri.x + ri.w);
    vzr = 0.5f * (rr.x - rr.w); vzi = 0.5f * (ri.x - ri.w);
    vxr = 0.5f * (rr.y + rr.z); vxi = 0.5f * (ri.y + ri.z);
    vyr = 0.5f * (ri.z - ri.y); vyi = 0.5f * (rr.y - rr.z);
    zacc = 0.0f;

    rot8(rowA, zacc, vxr, vyr, vzr, vxi, vyi, vzi);

    __syncthreads();             // done reading bufA
    CP_WAIT(0);                  // B1 done
    __syncthreads();

    phi_pass(rowB, s_w, s_t, 1);
    rot8(rowB, zacc, vxr, vyr, vzr, vxi, vyi, vzi);
    {   // final Rz(-zacc)
        float sz, cz;
        __sincosf(zacc, &sz, &cz);
        float nxr = cz * vxr + sz * vyr;
        float nyr = cz * vyr - sz * vxr;
        float nxi = cz * vxi + sz * vyi;
        float nyi = cz * vyi - sz * vxi;
        vxr = nxr; vyr = nyr; vxi = nxi; vyi = nyi;
    }

    // ---- store tile 1 ----
    if (act1) {
        if (full_complex) {
            long long ob = i1 * 8;
            if (ob + 7 < out_elems) {
                float4* op = (float4*)(out + ob);
                __stcs(op + 0, make_float4(t0r + vzr, t0i + vzi, vxr + vyi, vxi - vyr));
                __stcs(op + 1, make_float4(vxr - vyi, vxi + vyr, t0r - vzr, t0i - vzi));
            }
        } else {
            long long ob = i1 * 4;
            if (ob + 3 < out_elems) {
                __stcs((float4*)(out + ob),
                       make_float4(t0r + vzr, vxr + vyi, vxr - vyi, t0r - vzr));
            }
        }
    }
}

// ---- scalar fallback (any alignment) ---------------------------------------
__global__ void __launch_bounds__(128) qlayer_kernel_scalar(
    const float* __restrict__ rho_real,
    const float* __restrict__ rho_imag,
    const float* __restrict__ x,
    const float* __restrict__ w,
    const float* __restrict__ theta,
    float* __restrict__ out,
    long long nbatch,
    long long out_elems,
    int full_complex)
{
    __shared__ float s_w[48];
    __shared__ float s_t[48];
    int tid = threadIdx.x;
    if (tid < 48) {
        s_w[tid] = w[tid];
        s_t[tid] = theta[tid];
    }
    __syncthreads();

    long long i = (long long)blockIdx.x * 128 + tid;
    if (i >= nbatch) return;

    const float* xr = x + i * 48;
#define PHI(j) fmaf(xr[(j)], s_w[(j)], s_t[(j)])

    const float* rrp = rho_real + i * 4;
    const float* rip = rho_imag + i * 4;
    float rr0 = rrp[0], rr1 = rrp[1], rr2 = rrp[2], rr3 = rrp[3];
    float ri0 = rip[0], ri1 = rip[1], ri2 = rip[2], ri3 = rip[3];

    float t0r = 0.5f * (rr0 + rr3), t0i = 0.5f * (ri0 + ri3);
    float vzr = 0.5f * (rr0 - rr3), vzi = 0.5f * (ri0 - ri3);
    float vxr = 0.5f * (rr1 + rr2), vxi = 0.5f * (ri1 + ri2);
    float vyr = 0.5f * (ri2 - ri1), vyi = 0.5f * (rr1 - rr2);

    float zacc = 0.0f;
#pragma unroll
    for (int k = 0; k < 16; ++k) {
        float psi = zacc + PHI(3 * k + 2);
        float sz, cz;
        __sincosf(psi, &sz, &cz);
        {
            float nxr = cz * vxr + sz * vyr;
            float nyr = cz * vyr - sz * vxr;
            float nxi = cz * vxi + sz * vyi;
            float nyi = cz * vyi - sz * vxi;
            vxr = nxr; vyr = nyr; vxi = nxi; vyi = nyi;
        }
        float sy, cy;
        __sincosf(PHI(3 * k), &sy, &cy);
        {
            float nxr = cy * vxr + sy * vzr;
            float nzr = cy * vzr - sy * vxr;
            float nxi = cy * vxi + sy * vzi;
            float nzi = cy * vzi - sy * vxi;
            vxr = nxr; vzr = nzr; vxi = nxi; vzi = nzi;
        }
        zacc = PHI(3 * k + 1);
    }
    {
        float sz, cz;
        __sincosf(zacc, &sz, &cz);
        float nxr = cz * vxr + sz * vyr;
        float nyr = cz * vyr - sz * vxr;
        float nxi = cz * vxi + sz * vyi;
        float nyi = cz * vyi - sz * vxi;
        vxr = nxr; vyr = nyr; vxi = nxi; vyi = nyi;
    }
#undef PHI

    if (full_complex) {
        long long base = i * 8;
        if (base + 7 < out_elems) {
            out[base + 0] = t0r + vzr; out[base + 1] = t0i + vzi;
            out[base + 2] = vxr + vyi; out[base + 3] = vxi - vyr;
            out[base + 4] = vxr - vyi; out[base + 5] = vxi + vyr;
            out[base + 6] = t0r - vzr; out[base + 7] = t0i - vzi;
        }
    } else {
        long long base = i * 4;
        if (base + 3 < out_elems) {
            out[base + 0] = t0r + vzr;
            out[base + 1] = vxr + vyi;
            out[base + 2] = vxr - vyi;
            out[base + 3] = t0r - vzr;
        }
    }
}

extern "C" void kernel_launch(void* const* d_in, const int* in_sizes, int n_in,
                              void* d_out, int out_size)
{
    const float* rho_real = nullptr;
    const float* rho_imag = nullptr;
    const float* x = nullptr;
    const float* w = nullptr;
    const float* theta = nullptr;
    long long B = 0;

    // 1) Strict metadata order (rho_real, rho_imag, x, w, theta).
    if (n_in >= 5) {
        long long s0 = in_sizes[0], s1 = in_sizes[1], s2 = in_sizes[2];
        long long s3 = in_sizes[3], s4 = in_sizes[4];
        if (s0 == s1 && s0 > 0 && (s0 % 4) == 0 &&
            s2 == 12 * s0 && s3 == 48 && s4 == 48) {
            rho_real = (const float*)d_in[0];
            rho_imag = (const float*)d_in[1];
            x        = (const float*)d_in[2];
            w        = (const float*)d_in[3];
            theta    = (const float*)d_in[4];
            B = s0 / 4;
        }
    }

    // 2) Fallback: consistency search over sizes.
    if (B == 0) {
        for (int a = 0; a < n_in && B == 0; ++a) {
            for (int b = a + 1; b < n_in && B == 0; ++b) {
                long long sa = in_sizes[a], sb = in_sizes[b];
                if (sa != sb || sa <= 0 || (sa % 4) != 0) continue;
                long long Bc = sa / 4;
                if (Bc < 2) continue;
                int xk = -1;
                for (int c = 0; c < n_in; ++c) {
                    if (c == a || c == b) continue;
                    if ((long long)in_sizes[c] == 48LL * Bc) { xk = c; break; }
                }
                if (xk < 0) continue;
                int s1i = -1, s2i = -1;
                for (int c = 0; c < n_in; ++c) {
                    if (c == a || c == b || c == xk) continue;
                    if (in_sizes[c] == 48) {
                        if (s1i < 0) s1i = c;
                        else if (s2i < 0) { s2i = c; break; }
                    }
                }
                if (s1i < 0 || s2i < 0) continue;
                rho_real = (const float*)d_in[a];
                rho_imag = (const float*)d_in[b];
                x        = (const float*)d_in[xk];
                w        = (const float*)d_in[s1i];
                theta    = (const float*)d_in[s2i];
                B = Bc;
            }
        }
    }

    float* out = (float*)d_out;
    long long out_elems = (long long)out_size;
    int full_complex = (B > 0 && out_elems >= 8 * B) ? 1 : 0;

    bool aligned =
        (((uintptr_t)x        & 15) == 0) &&
        (((uintptr_t)rho_real & 15) == 0) &&
        (((uintptr_t)rho_imag & 15) == 0) &&
        (((uintptr_t)w        & 15) == 0) &&
        (((uintptr_t)theta    & 15) == 0) &&
        (((uintptr_t)out      & 15) == 0);

    if (B > 0 && aligned) {
        long long T = (B + 95) / 96;
        unsigned nblk = (unsigned)((T + 1) / 2);
        qlayer_kernel_vec<<<nblk, NTHREADS>>>(rho_real, rho_imag, x, w, theta, out,
                                              B, T, out_elems, full_complex);
    } else {
        unsigned nblk = (unsigned)(B > 0 ? (B + 127) / 128 : 1);
        qlayer_kernel_scalar<<<nblk, 128>>>(rho_real, rho_imag, x, w, theta, out,
                                            B, out_elems, full_complex);
    }
}